// round 6
// baseline (speedup 1.0000x reference)
#include <cuda_runtime.h>
#include <cstdint>

#define DMV  16
#define TILE 256
#define GX   56     // tiles strided per block; grid = (GX, B) -> 1792 blocks (~2 waves)

__device__ __forceinline__ float cayley_sign(int a, int b) {
    if (a & b & 8) return 0.0f;            // e3 * e3 = 0
    int s = 0;
    for (int t = a >> 1; t; t >>= 1) s += __popc(t & b);
    return (s & 1) ? -1.0f : 1.0f;
}
__device__ __forceinline__ uint32_t smem_u32(const void* p) {
    return (uint32_t)__cvta_generic_to_shared(p);
}
__device__ __forceinline__ void cp_async16(uint32_t s, const void* g) {
    asm volatile("cp.async.cg.shared.global [%0], [%1], 16;" :: "r"(s), "l"(g));
}

// ---------------------------------------------------------------------------
// Fused persistent kernel. Each block: (1) kick off cp.async of its first
// tile, (2) build per-l constants P (motor exp -> fused sandwich -> grade
// blocks + collapsed color vectors) in scratch aliasing buffer 1, (3) run a
// double-buffered tile pipeline: prefetch k+1 while computing/storing k.
// Swizzle: row r, float4-col c at (c ^ ((r>>1)&3)) — conflict-free both ways.
// ---------------------------------------------------------------------------
__global__ void __launch_bounds__(256, 6)
fused_kernel(const float* __restrict__ state,
             const float* __restrict__ instr,
             const float* __restrict__ remap,   // [4,10,10]
             const float* __restrict__ selw,    // [4,2]
             const float* __restrict__ selb,    // [4]
             float* __restrict__ out, int N)
{
    __shared__ __align__(16) float4 buf[2][TILE * 4];   // 2 x 16 KB
    __shared__ float P[112];
    // P layout: [0:16) G1 col-major {1,2,4,8} | [16:64) G2 col-major pad8
    // {3,5,6,9,10,12} | [64:80) G3 {7,11,13,14} | [80:90) bc | [96:106) b0

    const int l   = blockIdx.y;
    const int tid = threadIdx.x;
    const int a   = tid >> 4;
    const int b   = tid & 15;
    const int ntiles = (N + TILE - 1) / TILE;
    const int t0  = blockIdx.x;
    const int nT  = (t0 < ntiles) ? ((ntiles - 1 - t0) / GX + 1) : 0;

    const float4* gin  = reinterpret_cast<const float4*>(state) + (size_t)l * N * 4;
    float4*       gout = reinterpret_cast<float4*>(out)         + (size_t)l * N * 4;

    // ---- prologue: stage tile t0 into buf[0]; it flies while setup runs ----
    if (nT > 0) {
        const int nv = min(TILE, N - t0 * TILE);
        const float4* src = gin + (size_t)t0 * (TILE * 4);
        #pragma unroll
        for (int kk = 0; kk < 4; kk++) {
            int e = kk * 256 + tid, r = e >> 2, c = e & 3;
            if (r < nv) cp_async16(smem_u32(&buf[0][r*4 + (c ^ ((r>>1)&3))]), src + e);
        }
    }
    asm volatile("cp.async.commit_group;");

    // ---- setup: scratch aliases buf[1] (free until first prefetch) ----
    {
        float* scr = reinterpret_cast<float*>(&buf[1][0]);
        float* Z   = scr;          // [16][16]: Z[aa*16+lane] = xv[aa^lane]*sgn(aa,aa^lane)
        float* Lm  = scr + 256;
        float* Rm  = scr + 512;
        float* Sb  = scr + 768;
        float* xv  = scr + 1024;
        float* Mv  = scr + 1040;
        float* Mre = scr + 1056;
        float* wv  = scr + 1072;

        if (tid < 16)
            xv[tid] = (__popc(tid) == 2) ? -0.5f * instr[l * DMV + tid] : 0.0f;
        __syncthreads();
        Z[tid] = xv[a ^ b] * cayley_sign(a, a ^ b);
        __syncthreads();

        if (tid < 16) {            // 16-term Taylor exp, lanes 0..15 of warp 0
            float term = (tid == 0) ? 1.0f : 0.0f;
            float acc  = term;
            for (int n = 1; n < 16; n++) {
                float nt = 0.0f;
                #pragma unroll
                for (int aa = 0; aa < 16; aa++) {
                    float ta = __shfl_sync(0xFFFFu, term, aa);
                    nt = fmaf(ta, Z[aa * 16 + tid], nt);
                }
                term = nt / (float)n;
                acc += term;
            }
            Mv[tid] = acc;
            int g = __popc(tid);
            Mre[tid] = acc * ((((g * (g - 1) / 2) & 1) != 0) ? -1.0f : 1.0f);
        } else if (tid == 32) {    // selector softmax on a parallel warp
            float s0 = instr[l * DMV + 0], s1 = instr[l * DMV + 15];
            float lg[4], m = -3.4e38f;
            #pragma unroll
            for (int k = 0; k < 4; k++) {
                lg[k] = fmaf(s0, selw[k*2], fmaf(s1, selw[k*2+1], selb[k]));
                m = fmaxf(m, lg[k]);
            }
            float sum = 0.0f;
            #pragma unroll
            for (int k = 0; k < 4; k++) { lg[k] = expf(lg[k] - m); sum += lg[k]; }
            #pragma unroll
            for (int k = 0; k < 4; k++) wv[k] = lg[k] / sum;
        }
        __syncthreads();

        Lm[tid] = Mv[a ^ b]  * cayley_sign(a ^ b, a);
        Rm[tid] = Mre[a ^ b] * cayley_sign(a, a ^ b);
        __syncthreads();
        {
            float s = 0.0f;
            #pragma unroll
            for (int i = 0; i < 16; i++) s += Lm[a * 16 + i] * Rm[i * 16 + b];
            Sb[tid] = s;
        }
        __syncthreads();

        const int g1[4] = {1, 2, 4, 8};
        const int g2[6] = {3, 5, 6, 9, 10, 12};
        const int g3[4] = {7, 11, 13, 14};
        if (tid < 16) {
            int j = tid >> 2, i = tid & 3;
            P[tid] = Sb[g1[j] * 16 + g1[i]];
        } else if (tid < 64) {
            int t = tid - 16, j = t >> 3, i = t & 7;
            P[16 + t] = (i < 6) ? Sb[g2[j] * 16 + g2[i]] : 0.0f;
        } else if (tid < 80) {
            int t = tid - 64, j = t >> 2, i = t & 3;
            P[64 + t] = Sb[g3[j] * 16 + g3[i]];
        }
        if (tid < 10) {            // collapsed color vectors
            float bc = 0.0f, b0v = 0.0f;
            #pragma unroll
            for (int k = 0; k < 4; k++) {
                const float* tab = remap + k * 100 + tid * 10;
                float rowc = 0.0f;
                #pragma unroll
                for (int j = 0; j < 10; j++) rowc += tab[j] * (float)j;
                bc  += wv[k] * rowc;
                b0v += wv[k] * tab[0];
            }
            P[80 + tid] = bc;
            P[96 + tid] = b0v;
        }
        __syncthreads();           // P ready; scratch (buf[1]) now free
    }

    // ---- double-buffered tile pipeline ----
    for (int k = 0; k < nT; k++) {
        const int t   = t0 + k * GX;
        const int cur = k & 1;

        if (k + 1 < nT) {          // prefetch next tile into the other buffer
            const int tn = t + GX;
            const int nv = min(TILE, N - tn * TILE);
            const float4* src = gin + (size_t)tn * (TILE * 4);
            #pragma unroll
            for (int kk = 0; kk < 4; kk++) {
                int e = kk * 256 + tid, r = e >> 2, c = e & 3;
                if (r < nv) cp_async16(smem_u32(&buf[cur ^ 1][r*4 + (c ^ ((r>>1)&3))]), src + e);
            }
            asm volatile("cp.async.commit_group;");
            asm volatile("cp.async.wait_group 1;" ::: "memory");  // in-order: current done
        } else {
            asm volatile("cp.async.commit_group;");
            asm volatile("cp.async.wait_group 0;" ::: "memory");  // last tile: drain all
        }
        __syncthreads();

        {   // compute one row per thread from buf[cur], write back in place
            const int r  = tid;
            const int sw = (r >> 1) & 3;
            float4 v0 = buf[cur][r * 4 + (0 ^ sw)];
            float4 v1 = buf[cur][r * 4 + (1 ^ sw)];
            float4 v2 = buf[cur][r * 4 + (2 ^ sw)];
            float4 v3 = buf[cur][r * 4 + (3 ^ sw)];

            const float x0 = v0.x, x1 = v0.y, x2  = v0.z, x3  = v0.w;
            const float x4 = v1.x, x5 = v1.y, x6  = v1.z, x7  = v1.w;
            const float x8 = v2.x, x9 = v2.y, x10 = v2.z, x11 = v2.w;
            const float x12 = v3.x, x13 = v3.y, x14 = v3.z;   // x15 unused

            const float4* P4 = reinterpret_cast<const float4*>(P);

            // grade-1 block
            float4 a0 = P4[0], a1 = P4[1], a2 = P4[2], a3 = P4[3];
            float y1 = fmaf(x8, a3.x, fmaf(x4, a2.x, fmaf(x2, a1.x, x1 * a0.x)));
            float y2 = fmaf(x8, a3.y, fmaf(x4, a2.y, fmaf(x2, a1.y, x1 * a0.y)));
            float y4 = fmaf(x8, a3.z, fmaf(x4, a2.z, fmaf(x2, a1.z, x1 * a0.z)));
            float y8 = fmaf(x8, a3.w, fmaf(x4, a2.w, fmaf(x2, a1.w, x1 * a0.w)));

            // grade-2 block
            float y3, y5, y6, y9, y10, y12;
            {
                float4 cA = P4[4], cB = P4[5];
                y3 = x3 * cA.x; y5 = x3 * cA.y; y6  = x3 * cA.z;
                y9 = x3 * cA.w; y10 = x3 * cB.x; y12 = x3 * cB.y;
            }
            {
                float4 cA = P4[6], cB = P4[7];
                y3 = fmaf(x5, cA.x, y3); y5  = fmaf(x5, cA.y, y5);  y6  = fmaf(x5, cA.z, y6);
                y9 = fmaf(x5, cA.w, y9); y10 = fmaf(x5, cB.x, y10); y12 = fmaf(x5, cB.y, y12);
            }
            {
                float4 cA = P4[8], cB = P4[9];
                y3 = fmaf(x6, cA.x, y3); y5  = fmaf(x6, cA.y, y5);  y6  = fmaf(x6, cA.z, y6);
                y9 = fmaf(x6, cA.w, y9); y10 = fmaf(x6, cB.x, y10); y12 = fmaf(x6, cB.y, y12);
            }
            {
                float4 cA = P4[10], cB = P4[11];
                y3 = fmaf(x9, cA.x, y3); y5  = fmaf(x9, cA.y, y5);  y6  = fmaf(x9, cA.z, y6);
                y9 = fmaf(x9, cA.w, y9); y10 = fmaf(x9, cB.x, y10); y12 = fmaf(x9, cB.y, y12);
            }
            {
                float4 cA = P4[12], cB = P4[13];
                y3 = fmaf(x10, cA.x, y3); y5  = fmaf(x10, cA.y, y5);  y6  = fmaf(x10, cA.z, y6);
                y9 = fmaf(x10, cA.w, y9); y10 = fmaf(x10, cB.x, y10); y12 = fmaf(x10, cB.y, y12);
            }
            {
                float4 cA = P4[14], cB = P4[15];
                y3 = fmaf(x12, cA.x, y3); y5  = fmaf(x12, cA.y, y5);  y6  = fmaf(x12, cA.z, y6);
                y9 = fmaf(x12, cA.w, y9); y10 = fmaf(x12, cB.x, y10); y12 = fmaf(x12, cB.y, y12);
            }

            // grade-3 block
            float4 h0 = P4[16], h1 = P4[17], h2 = P4[18], h3 = P4[19];
            float y7  = fmaf(x14, h3.x, fmaf(x13, h2.x, fmaf(x11, h1.x, x7 * h0.x)));
            float y11 = fmaf(x14, h3.y, fmaf(x13, h2.y, fmaf(x11, h1.y, x7 * h0.y)));
            float y13 = fmaf(x14, h3.z, fmaf(x13, h2.z, fmaf(x11, h1.z, x7 * h0.z)));
            float y14 = fmaf(x14, h3.w, fmaf(x13, h2.w, fmaf(x11, h1.w, x7 * h0.w)));

            // color unit from x0 (y0 == x0: M~M = 1, grade preserved)
            float raw = x0 * 9.0f;
            float cc = fminf(fmaxf(rintf(raw), 0.0f), 9.0f);
            float dm = raw - cc;
            float m = -4.0f * dm * dm;              // exact max of the 10 logits
            float se = 0.0f, nc = 0.0f, n0 = 0.0f;
            #pragma unroll
            for (int i = 0; i < 10; i++) {
                float ti = raw - (float)i;
                float e = __expf(fmaf(-4.0f * ti, ti, -m));
                se += e;
                nc = fmaf(e, P[80 + i], nc);
                n0 = fmaf(e, P[96 + i], n0);
            }
            float inv = 1.0f / se;
            float out0  = nc * inv * (1.0f / 9.0f);
            float out15 = 1.0f - n0 * inv;

            buf[cur][r * 4 + (0 ^ sw)] = make_float4(out0, y1,  y2,  y3);
            buf[cur][r * 4 + (1 ^ sw)] = make_float4(y4,   y5,  y6,  y7);
            buf[cur][r * 4 + (2 ^ sw)] = make_float4(y8,   y9,  y10, y11);
            buf[cur][r * 4 + (3 ^ sw)] = make_float4(y12,  y13, y14, out15);
        }
        __syncthreads();

        {   // stage out: swizzled LDS -> coalesced streaming STG
            const int nv = min(TILE, N - t * TILE);
            float4* dst = gout + (size_t)t * (TILE * 4);
            #pragma unroll
            for (int kk = 0; kk < 4; kk++) {
                int e = kk * 256 + tid, r = e >> 2, c = e & 3;
                if (r < nv) __stcs(dst + e, buf[cur][r*4 + (c ^ ((r>>1)&3))]);
            }
        }
        __syncthreads();   // buf[cur] free before it is prefetched into (k+2)
    }
}

extern "C" void kernel_launch(void* const* d_in, const int* in_sizes, int n_in,
                              void* d_out, int out_size)
{
    const float* state = (const float*)d_in[0];
    const float* instr = (const float*)d_in[1];
    const float* remap = (const float*)d_in[2];
    const float* selw  = (const float*)d_in[3];
    const float* selb  = (const float*)d_in[4];
    float* out = (float*)d_out;

    const int B = in_sizes[1] / DMV;            // 32
    const int N = in_sizes[0] / in_sizes[1];    // 100000

    dim3 grid(GX, B);
    fused_kernel<<<grid, 256>>>(state, instr, remap, selw, selb, out, N);
}